// round 11
// baseline (speedup 1.0000x reference)
#include <cuda_runtime.h>
#include <cuda_bf16.h>
#include <math.h>
#include <stdint.h>

#define N_ENT_MAX 150016
#define H 128
#define DEG 32
#define TOPK 10
#define TILE_M 64
#define K_PAD 136     // bf16 elems per smem row (272B) -> conflict-free ldmatrix
#define D_PAD 132     // f32 elems per D smem row

// -------- device scratch (no allocs allowed) --------
__device__ float g_h_node[N_ENT_MAX * H];
__device__ float g_s_src[N_ENT_MAX];
__device__ float g_s_dst[N_ENT_MAX];
__device__ float g_h_rel[512 * H];
__device__ float g_s_rel[512];
// Pre-transposed B operands: B[n][k] = Wmat[k][n], bf16 hi/lo, rows padded to K_PAD
__device__ __align__(16) __nv_bfloat16 g_BW_hi[H * K_PAD];
__device__ __align__(16) __nv_bfloat16 g_BW_lo[H * K_PAD];
__device__ __align__(16) __nv_bfloat16 g_BN_hi[H * K_PAD];
__device__ __align__(16) __nv_bfloat16 g_BN_lo[H * K_PAD];

// ---------------- helpers ---------------------------
__device__ __forceinline__ uint32_t smem_u32(const void* p) {
    uint32_t a;
    asm("{ .reg .u64 t; cvta.to.shared.u64 t, %1; cvt.u32.u64 %0, t; }"
        : "=r"(a) : "l"(p));
    return a;
}

#define LDMX4(r0, r1, r2, r3, addr)                                             \
    asm volatile("ldmatrix.sync.aligned.m8n8.x4.shared.b16 {%0,%1,%2,%3}, [%4];"\
                 : "=r"(r0), "=r"(r1), "=r"(r2), "=r"(r3) : "r"(addr))

__device__ __forceinline__ void mma16816(float* c, uint32_t a0, uint32_t a1,
                                         uint32_t a2, uint32_t a3,
                                         uint32_t b0, uint32_t b1) {
    asm volatile(
        "mma.sync.aligned.m16n8k16.row.col.f32.bf16.bf16.f32 "
        "{%0,%1,%2,%3}, {%4,%5,%6,%7}, {%8,%9}, {%0,%1,%2,%3};"
        : "+f"(c[0]), "+f"(c[1]), "+f"(c[2]), "+f"(c[3])
        : "r"(a0), "r"(a1), "r"(a2), "r"(a3), "r"(b0), "r"(b1));
}

// ============ prep: B[n][k] = src[k][n] as bf16 hi/lo ======================
__global__ void kprepB(const float* __restrict__ W, const float* __restrict__ NW) {
    int tid = blockIdx.x * blockDim.x + threadIdx.x;
    if (tid >= H * H) return;
    int k = tid >> 7, nn = tid & 127;
    int off = nn * K_PAD + k;
    {
        float f = W[tid];
        __nv_bfloat16 hi = __float2bfloat16_rn(f);
        g_BW_hi[off] = hi;
        g_BW_lo[off] = __float2bfloat16_rn(f - __bfloat162float(hi));
    }
    {
        float f = NW[tid];
        __nv_bfloat16 hi = __float2bfloat16_rn(f);
        g_BN_hi[off] = hi;
        g_BN_lo[off] = __float2bfloat16_rn(f - __bfloat162float(hi));
    }
}

// -------- shared smem layout for both big kernels --------
#define SM_BHI 0
#define SM_BLO 34816
#define SM_A   69632
#define SM_ALO 87040
#define SM_A1  104448
#define SM_A2  104960
#define SM_ST  104448       // kattend: per-warp topk staging (reuses a1/a2 area)
#define SM_TOTAL 106496
#define GRID_GEMM 296       // 148 SMs x 2

// ====== kgemm0: h_node = ent_emb @ W + s_src/s_dst (+inline krel) =========
__global__ void __launch_bounds__(256) kgemm0(const float* __restrict__ Xin,
                                              const float* __restrict__ avec,
                                              const float* __restrict__ rel_emb,
                                              const float* __restrict__ W_r,
                                              int n, int ntiles, int nrel) {
    extern __shared__ char sm[];
    uint32_t sb = smem_u32(sm);
    float* a1s = (float*)(sm + SM_A1);
    float* a2s = (float*)(sm + SM_A2);
    float* D = (float*)(sm + SM_A);
    __nv_bfloat16* Ahi = (__nv_bfloat16*)(sm + SM_A);
    __nv_bfloat16* Alo = (__nv_bfloat16*)(sm + SM_ALO);
    int tid = threadIdx.x;
    int w = tid >> 5, l = tid & 31;
    int wm = w >> 2, wn = w & 3;
    int quad = l >> 3, lrow = l & 7;

    if (tid < 128) { a1s[tid] = avec[tid]; a2s[tid] = avec[H + tid]; }

    // ---- inline krel: blocks 0..(nrel+1)/2-1 handle 2 relations each ----
    if (blockIdx.x < (nrel + 1) / 2) {
        int rr = blockIdx.x * 2 + (tid >> 7);
        int j = tid & 127;
        if (rr < nrel) {
            const float* x = rel_emb + rr * H;
            float acc = 0.f;
#pragma unroll 8
            for (int h = 0; h < H; ++h) acc = fmaf(x[h], W_r[h * H + j], acc);
            g_h_rel[rr * H + j] = acc;
            float p = acc * avec[2 * H + j];
#pragma unroll
            for (int off = 16; off; off >>= 1) p += __shfl_xor_sync(0xffffffffu, p, off);
            if ((tid & 31) == 0) D[tid >> 5] = p;
        }
        __syncthreads();
        if ((tid & 127) == 0 && rr < nrel) {
            int b = (tid >> 7) * 4;
            g_s_rel[rr] = D[b] + D[b + 1] + D[b + 2] + D[b + 3];
        }
    }

    // ---- stage B once ----
    {
        const uint4* bh = (const uint4*)(const void*)g_BW_hi;
        const uint4* bl = (const uint4*)(const void*)g_BW_lo;
        uint4* dh = (uint4*)(sm + SM_BHI);
        uint4* dl = (uint4*)(sm + SM_BLO);
        for (int i = tid; i < (H * K_PAD * 2) / 16; i += 256) { dh[i] = bh[i]; dl[i] = bl[i]; }
    }

    const float4* X4 = (const float4*)Xin;
    uint32_t a_loff = (uint32_t)(((lrow + (quad & 1) * 8) * K_PAD + (quad >> 1) * 8) * 2);
    uint32_t b_loff = (uint32_t)(((lrow + (quad >> 1) * 8) * K_PAD + (quad & 1) * 8) * 2);

    float4 pre[8];
    {
        int t0 = blockIdx.x, row0 = t0 * TILE_M;
#pragma unroll
        for (int it = 0; it < 8; ++it) {
            int idx = it * 256 + tid;
            int r = idx >> 5, s = idx & 31;
            int row = row0 + r;
            pre[it] = make_float4(0.f, 0.f, 0.f, 0.f);
            if (t0 < ntiles && row < n) pre[it] = X4[(size_t)row * 32 + s];
        }
    }

    for (int t = blockIdx.x; t < ntiles; t += GRID_GEMM) {
        int row0 = t * TILE_M;
        __syncthreads();

#pragma unroll
        for (int it = 0; it < 8; ++it) {
            int idx = it * 256 + tid;
            int r = idx >> 5, s = idx & 31;
            float4 v = pre[it];
            __nv_bfloat16 h0 = __float2bfloat16_rn(v.x);
            __nv_bfloat16 h1 = __float2bfloat16_rn(v.y);
            __nv_bfloat16 h2 = __float2bfloat16_rn(v.z);
            __nv_bfloat16 h3 = __float2bfloat16_rn(v.w);
            __nv_bfloat162 ph0 = __halves2bfloat162(h0, h1);
            __nv_bfloat162 ph1 = __halves2bfloat162(h2, h3);
            uint2 uh; uh.x = *(uint32_t*)&ph0; uh.y = *(uint32_t*)&ph1;
            *(uint2*)(Ahi + r * K_PAD + 4 * s) = uh;
            __nv_bfloat162 pl0 = __halves2bfloat162(
                __float2bfloat16_rn(v.x - __bfloat162float(h0)),
                __float2bfloat16_rn(v.y - __bfloat162float(h1)));
            __nv_bfloat162 pl1 = __halves2bfloat162(
                __float2bfloat16_rn(v.z - __bfloat162float(h2)),
                __float2bfloat16_rn(v.w - __bfloat162float(h3)));
            uint2 ul; ul.x = *(uint32_t*)&pl0; ul.y = *(uint32_t*)&pl1;
            *(uint2*)(Alo + r * K_PAD + 4 * s) = ul;
        }
        __syncthreads();

        {
            int tn = t + GRID_GEMM, nrow0 = tn * TILE_M;
#pragma unroll
            for (int it = 0; it < 8; ++it) {
                int idx = it * 256 + tid;
                int r = idx >> 5, s = idx & 31;
                int row = nrow0 + r;
                pre[it] = make_float4(0.f, 0.f, 0.f, 0.f);
                if (tn < ntiles && row < n) pre[it] = X4[(size_t)row * 32 + s];
            }
        }

        float acc[2][4][4];
#pragma unroll
        for (int i = 0; i < 2; i++)
#pragma unroll
            for (int j = 0; j < 4; j++)
#pragma unroll
                for (int q = 0; q < 4; q++) acc[i][j][q] = 0.f;

#pragma unroll
        for (int pass = 0; pass < 3; pass++) {
            uint32_t abase = sb + ((pass == 2) ? SM_ALO : SM_A);
            uint32_t bbase = sb + ((pass == 1) ? SM_BLO : SM_BHI);
            uint32_t arow = abase + (uint32_t)(wm * 32) * (K_PAD * 2) + a_loff;
            uint32_t brow = bbase + (uint32_t)(wn * 32) * (K_PAD * 2) + b_loff;
#pragma unroll
            for (int ks = 0; ks < 8; ks++) {
                uint32_t k0 = ks * 32;
                uint32_t af[2][4], bf[2][4];
#pragma unroll
                for (int mt = 0; mt < 2; mt++)
                    LDMX4(af[mt][0], af[mt][1], af[mt][2], af[mt][3],
                          arow + (uint32_t)(mt * 16) * (K_PAD * 2) + k0);
#pragma unroll
                for (int nt = 0; nt < 2; nt++)
                    LDMX4(bf[nt][0], bf[nt][1], bf[nt][2], bf[nt][3],
                          brow + (uint32_t)(nt * 16) * (K_PAD * 2) + k0);
#pragma unroll
                for (int mt = 0; mt < 2; mt++)
#pragma unroll
                    for (int q = 0; q < 4; q++)
                        mma16816(acc[mt][q], af[mt][0], af[mt][1], af[mt][2], af[mt][3],
                                 bf[q >> 1][(q & 1) * 2], bf[q >> 1][(q & 1) * 2 + 1]);
            }
        }
        __syncthreads();

#pragma unroll
        for (int mt = 0; mt < 2; mt++) {
            int row = wm * 32 + mt * 16 + (l >> 2);
#pragma unroll
            for (int q = 0; q < 4; q++) {
                int col = wn * 32 + q * 8 + 2 * (l & 3);
                *(float2*)(D + row * D_PAD + col) = make_float2(acc[mt][q][0], acc[mt][q][1]);
                *(float2*)(D + (row + 8) * D_PAD + col) = make_float2(acc[mt][q][2], acc[mt][q][3]);
            }
        }
        __syncthreads();

#pragma unroll
        for (int it = 0; it < 8; ++it) {
            int idx = it * 256 + tid;
            int r = idx >> 5, s = idx & 31;
            int row = row0 + r;
            if (row < n) {
                float4 v = *(float4*)(D + r * D_PAD + 4 * s);
                *(float4*)(g_h_node + (size_t)row * H + 4 * s) = v;
            }
        }
        if (tid < 128) {
            int r = tid & 63;
            int row = row0 + r;
            if (row < n) {
                const float* av = (tid < 64) ? a1s : a2s;
                float p = 0.f;
                const float* dr = D + r * D_PAD;
#pragma unroll 8
                for (int c = 0; c < H; c++) p = fmaf(dr[c], av[c], p);
                if (tid < 64) g_s_src[row] = p; else g_s_dst[row] = p;
            }
        }
    }
}

// ====== kattend: fused score->top10->softmax->gather->MMA->tanh ===========
// Per 64-row tile: 8 warps x 8 nodes each. Gather result written directly
// into the smem A-tile as bf16 hi/lo; then 3-pass MMA with g_BN; tanh out.
__global__ void __launch_bounds__(256, 2) kattend(const int* __restrict__ src,
                                                  const int* __restrict__ rid,
                                                  float* __restrict__ out,
                                                  int n, int ntiles) {
    extern __shared__ char sm[];
    uint32_t sb = smem_u32(sm);
    float* D = (float*)(sm + SM_A);
    __nv_bfloat16* Ahi = (__nv_bfloat16*)(sm + SM_A);
    __nv_bfloat16* Alo = (__nv_bfloat16*)(sm + SM_ALO);
    int tid = threadIdx.x;
    int w = tid >> 5, l = tid & 31;
    int wm = w >> 2, wn = w & 3;
    int quad = l >> 3, lrow = l & 7;
    // per-warp topk staging: 16 attn + 16 sk + 16 rk per warp
    float* atw = (float*)(sm + SM_ST) + w * 48;
    int*   skw = (int*)(atw + 16);
    int*   rkw = skw + 16;

    // ---- stage B once ----
    {
        const uint4* bh = (const uint4*)(const void*)g_BN_hi;
        const uint4* bl = (const uint4*)(const void*)g_BN_lo;
        uint4* dh = (uint4*)(sm + SM_BHI);
        uint4* dl = (uint4*)(sm + SM_BLO);
        for (int i = tid; i < (H * K_PAD * 2) / 16; i += 256) { dh[i] = bh[i]; dl[i] = bl[i]; }
    }

    uint32_t a_loff = (uint32_t)(((lrow + (quad & 1) * 8) * K_PAD + (quad >> 1) * 8) * 2);
    uint32_t b_loff = (uint32_t)(((lrow + (quad >> 1) * 8) * K_PAD + (quad & 1) * 8) * 2);

    for (int t = blockIdx.x; t < ntiles; t += GRID_GEMM) {
        int row0 = t * TILE_M;
        __syncthreads();                 // prev D reads done / B ready

        // ---- gather phase: each warp builds 8 rows of the A tile ----
#pragma unroll 1
        for (int i = 0; i < 8; i++) {
            int r = w * 8 + i;
            int node = row0 + r;
            float4 acc = make_float4(0.f, 0.f, 0.f, 0.f);
            if (node < n) {
                float sdst = g_s_dst[node];
                int s = src[node * DEG + l];
                int rr = rid[node * DEG + l];
                float v = (g_s_src[s] + sdst) + g_s_rel[rr];
                float sc = (v >= 0.f) ? v : 0.2f * v;

                int rank = 0;
#pragma unroll
                for (int j = 0; j < DEG; j++) {
                    float vj = __shfl_sync(0xffffffffu, sc, j);
                    rank += (vj > sc) || (vj == sc && j < l);
                }
                bool sel = (rank < TOPK);

                float m = sel ? sc : __int_as_float(0xff800000);
#pragma unroll
                for (int off = 16; off; off >>= 1)
                    m = fmaxf(m, __shfl_xor_sync(0xffffffffu, m, off));
                float e = sel ? expf(sc - m) : 0.f;
                float z = e;
#pragma unroll
                for (int off = 16; off; off >>= 1)
                    z += __shfl_xor_sync(0xffffffffu, z, off);
                float attn = e / z;

                if (sel) { atw[rank] = attn; skw[rank] = s; rkw[rank] = rr; }
                __syncwarp();

#pragma unroll
                for (int k = 0; k < TOPK; k++) {
                    int sk = skw[k], rk = rkw[k];
                    float ak = atw[k];
                    float4 hn = __ldcg((const float4*)(g_h_node + (size_t)sk * H + 4 * l));
                    float4 hr = *(const float4*)(g_h_rel + rk * H + 4 * l);
                    acc.x = fmaf(ak, hn.x + hr.x, acc.x);
                    acc.y = fmaf(ak, hn.y + hr.y, acc.y);
                    acc.z = fmaf(ak, hn.z + hr.z, acc.z);
                    acc.w = fmaf(ak, hn.w + hr.w, acc.w);
                }
                __syncwarp();
            }
            // convert to bf16 hi/lo, write A-tile row r (dims 4l..4l+3)
            __nv_bfloat16 h0 = __float2bfloat16_rn(acc.x);
            __nv_bfloat16 h1 = __float2bfloat16_rn(acc.y);
            __nv_bfloat16 h2 = __float2bfloat16_rn(acc.z);
            __nv_bfloat16 h3 = __float2bfloat16_rn(acc.w);
            __nv_bfloat162 ph0 = __halves2bfloat162(h0, h1);
            __nv_bfloat162 ph1 = __halves2bfloat162(h2, h3);
            uint2 uh; uh.x = *(uint32_t*)&ph0; uh.y = *(uint32_t*)&ph1;
            *(uint2*)(Ahi + r * K_PAD + 4 * l) = uh;
            __nv_bfloat162 pl0 = __halves2bfloat162(
                __float2bfloat16_rn(acc.x - __bfloat162float(h0)),
                __float2bfloat16_rn(acc.y - __bfloat162float(h1)));
            __nv_bfloat162 pl1 = __halves2bfloat162(
                __float2bfloat16_rn(acc.z - __bfloat162float(h2)),
                __float2bfloat16_rn(acc.w - __bfloat162float(h3)));
            uint2 ul; ul.x = *(uint32_t*)&pl0; ul.y = *(uint32_t*)&pl1;
            *(uint2*)(Alo + r * K_PAD + 4 * l) = ul;
        }
        __syncthreads();

        // ---- 3-pass warp MMA: AhBh + AhBl + AlBh ----
        float acc[2][4][4];
#pragma unroll
        for (int i = 0; i < 2; i++)
#pragma unroll
            for (int j = 0; j < 4; j++)
#pragma unroll
                for (int q = 0; q < 4; q++) acc[i][j][q] = 0.f;

#pragma unroll
        for (int pass = 0; pass < 3; pass++) {
            uint32_t abase = sb + ((pass == 2) ? SM_ALO : SM_A);
            uint32_t bbase = sb + ((pass == 1) ? SM_BLO : SM_BHI);
            uint32_t arow = abase + (uint32_t)(wm * 32) * (K_PAD * 2) + a_loff;
            uint32_t brow = bbase + (uint32_t)(wn * 32) * (K_PAD * 2) + b_loff;
#pragma unroll
            for (int ks = 0; ks < 8; ks++) {
                uint32_t k0 = ks * 32;
                uint32_t af[2][4], bf[2][4];
#pragma unroll
                for (int mt = 0; mt < 2; mt++)
                    LDMX4(af[mt][0], af[mt][1], af[mt][2], af[mt][3],
                          arow + (uint32_t)(mt * 16) * (K_PAD * 2) + k0);
#pragma unroll
                for (int nt = 0; nt < 2; nt++)
                    LDMX4(bf[nt][0], bf[nt][1], bf[nt][2], bf[nt][3],
                          brow + (uint32_t)(nt * 16) * (K_PAD * 2) + k0);
#pragma unroll
                for (int mt = 0; mt < 2; mt++)
#pragma unroll
                    for (int q = 0; q < 4; q++)
                        mma16816(acc[mt][q], af[mt][0], af[mt][1], af[mt][2], af[mt][3],
                                 bf[q >> 1][(q & 1) * 2], bf[q >> 1][(q & 1) * 2 + 1]);
            }
        }
        __syncthreads();

        // ---- frags -> D smem ----
#pragma unroll
        for (int mt = 0; mt < 2; mt++) {
            int row = wm * 32 + mt * 16 + (l >> 2);
#pragma unroll
            for (int q = 0; q < 4; q++) {
                int col = wn * 32 + q * 8 + 2 * (l & 3);
                *(float2*)(D + row * D_PAD + col) = make_float2(acc[mt][q][0], acc[mt][q][1]);
                *(float2*)(D + (row + 8) * D_PAD + col) = make_float2(acc[mt][q][2], acc[mt][q][3]);
            }
        }
        __syncthreads();

        // ---- tanh epilogue ----
#pragma unroll
        for (int it = 0; it < 8; ++it) {
            int idx = it * 256 + tid;
            int r = idx >> 5, s = idx & 31;
            int row = row0 + r;
            if (row < n) {
                float4 v = *(float4*)(D + r * D_PAD + 4 * s);
                *(float4*)(out + (size_t)row * H + 4 * s) =
                    make_float4(tanhf(v.x), tanhf(v.y), tanhf(v.z), tanhf(v.w));
            }
        }
    }
}

// ============================== launch =====================================
extern "C" void kernel_launch(void* const* d_in, const int* in_sizes, int n_in,
                              void* d_out, int out_size) {
    const float* ent = (const float*)d_in[0];
    const float* rel = (const float*)d_in[1];
    const float* W   = (const float*)d_in[2];
    const float* W_r = (const float*)d_in[3];
    const float* a   = (const float*)d_in[4];
    const float* nw  = (const float*)d_in[5];
    const int*   src = (const int*)d_in[6];
    const int*   rid = (const int*)d_in[7];
    float* out = (float*)d_out;

    int n    = in_sizes[0] / H;   // 150000
    int nrel = in_sizes[1] / H;   // 500
    int ntiles = (n + TILE_M - 1) / TILE_M;

    cudaFuncSetAttribute(kgemm0,  cudaFuncAttributeMaxDynamicSharedMemorySize, SM_TOTAL);
    cudaFuncSetAttribute(kattend, cudaFuncAttributeMaxDynamicSharedMemorySize, SM_TOTAL);

    kprepB<<<(H * H + 255) / 256, 256>>>(W, nw);
    kgemm0<<<GRID_GEMM, 256, SM_TOTAL>>>(ent, a, rel, W_r, n, ntiles, nrel);
    kattend<<<GRID_GEMM, 256, SM_TOTAL>>>(src, rid, out, n, ntiles);
}

// round 12
// speedup vs baseline: 1.3148x; 1.3148x over previous
#include <cuda_runtime.h>
#include <cuda_bf16.h>
#include <math.h>
#include <stdint.h>

#define N_ENT_MAX 150016
#define H 128
#define DEG 32
#define TOPK 10
#define TILE_M 64
#define K_PAD 136     // bf16 elems per smem row (272B) -> conflict-free ldmatrix
#define D_PAD 132     // f32 elems per D smem row

// -------- device scratch (no allocs allowed) --------
__device__ float g_h_node[N_ENT_MAX * H];
__device__ float g_s_src[N_ENT_MAX];
__device__ float g_s_dst[N_ENT_MAX];
__device__ float g_h_rel[512 * H];
__device__ float g_s_rel[512];
// neigh, pre-split to bf16 hi/lo by kgather (identical values to a later split)
__device__ __align__(16) __nv_bfloat16 g_nA_hi[N_ENT_MAX * H];
__device__ __align__(16) __nv_bfloat16 g_nA_lo[N_ENT_MAX * H];

// ---------------- helpers ---------------------------
__device__ __forceinline__ uint32_t smem_u32(const void* p) {
    uint32_t a;
    asm("{ .reg .u64 t; cvta.to.shared.u64 t, %1; cvt.u32.u64 %0, t; }"
        : "=r"(a) : "l"(p));
    return a;
}

#define LDMX4(r0, r1, r2, r3, addr)                                             \
    asm volatile("ldmatrix.sync.aligned.m8n8.x4.shared.b16 {%0,%1,%2,%3}, [%4];"\
                 : "=r"(r0), "=r"(r1), "=r"(r2), "=r"(r3) : "r"(addr))

__device__ __forceinline__ void mma16816(float* c, uint32_t a0, uint32_t a1,
                                         uint32_t a2, uint32_t a3,
                                         uint32_t b0, uint32_t b1) {
    asm volatile(
        "mma.sync.aligned.m16n8k16.row.col.f32.bf16.bf16.f32 "
        "{%0,%1,%2,%3}, {%4,%5,%6,%7}, {%8,%9}, {%0,%1,%2,%3};"
        : "+f"(c[0]), "+f"(c[1]), "+f"(c[2]), "+f"(c[3])
        : "r"(a0), "r"(a1), "r"(a2), "r"(a3), "r"(b0), "r"(b1));
}

// -------- shared smem layout for both GEMM kernels --------
#define SM_BHI 0
#define SM_BLO 34816
#define SM_A   69632
#define SM_ALO 87040
#define SM_A1  104448
#define SM_A2  104960
#define SM_TOTAL 106496
#define GRID_GEMM 296       // 148 SMs x 2

// convert Wmat[k][n] (row-major fp32) -> smem B[n][k] bf16 hi/lo
__device__ __forceinline__ void stage_B_from(const float* __restrict__ Wm,
                                             __nv_bfloat16* Bhi,
                                             __nv_bfloat16* Blo, int tid) {
    for (int i = tid; i < H * H; i += 256) {
        int k = i >> 7, nn = i & 127;
        float f = Wm[i];
        __nv_bfloat16 hi = __float2bfloat16_rn(f);
        Bhi[nn * K_PAD + k] = hi;
        Blo[nn * K_PAD + k] = __float2bfloat16_rn(f - __bfloat162float(hi));
    }
}

// ====== kgemm0: h_node = ent_emb @ W + s_src/s_dst (+inline krel) =========
__global__ void __launch_bounds__(256) kgemm0(const float* __restrict__ Xin,
                                              const float* __restrict__ avec,
                                              const float* __restrict__ rel_emb,
                                              const float* __restrict__ W_r,
                                              const float* __restrict__ W,
                                              int n, int ntiles, int nrel) {
    extern __shared__ char sm[];
    uint32_t sb = smem_u32(sm);
    float* a1s = (float*)(sm + SM_A1);
    float* a2s = (float*)(sm + SM_A2);
    float* D = (float*)(sm + SM_A);
    __nv_bfloat16* Ahi = (__nv_bfloat16*)(sm + SM_A);
    __nv_bfloat16* Alo = (__nv_bfloat16*)(sm + SM_ALO);
    int tid = threadIdx.x;
    int w = tid >> 5, l = tid & 31;
    int wm = w >> 2, wn = w & 3;
    int quad = l >> 3, lrow = l & 7;

    if (tid < 128) { a1s[tid] = avec[tid]; a2s[tid] = avec[H + tid]; }

    // ---- inline krel: blocks 0..(nrel+1)/2-1 handle 2 relations each ----
    if (blockIdx.x < (nrel + 1) / 2) {
        int rr = blockIdx.x * 2 + (tid >> 7);
        int j = tid & 127;
        if (rr < nrel) {
            const float* x = rel_emb + rr * H;
            float acc = 0.f;
#pragma unroll 8
            for (int h = 0; h < H; ++h) acc = fmaf(x[h], W_r[h * H + j], acc);
            g_h_rel[rr * H + j] = acc;
            float p = acc * avec[2 * H + j];
#pragma unroll
            for (int off = 16; off; off >>= 1) p += __shfl_xor_sync(0xffffffffu, p, off);
            if ((tid & 31) == 0) D[tid >> 5] = p;
        }
        __syncthreads();
        if ((tid & 127) == 0 && rr < nrel) {
            int b = (tid >> 7) * 4;
            g_s_rel[rr] = D[b] + D[b + 1] + D[b + 2] + D[b + 3];
        }
        __syncthreads();
    }

    // ---- stage B once (convert W inline) ----
    stage_B_from(W, (__nv_bfloat16*)(sm + SM_BHI), (__nv_bfloat16*)(sm + SM_BLO), tid);

    const float4* X4 = (const float4*)Xin;
    uint32_t a_loff = (uint32_t)(((lrow + (quad & 1) * 8) * K_PAD + (quad >> 1) * 8) * 2);
    uint32_t b_loff = (uint32_t)(((lrow + (quad >> 1) * 8) * K_PAD + (quad & 1) * 8) * 2);

    float4 pre[8];
    {
        int t0 = blockIdx.x, row0 = t0 * TILE_M;
#pragma unroll
        for (int it = 0; it < 8; ++it) {
            int idx = it * 256 + tid;
            int r = idx >> 5, s = idx & 31;
            int row = row0 + r;
            pre[it] = make_float4(0.f, 0.f, 0.f, 0.f);
            if (t0 < ntiles && row < n) pre[it] = X4[(size_t)row * 32 + s];
        }
    }

    for (int t = blockIdx.x; t < ntiles; t += GRID_GEMM) {
        int row0 = t * TILE_M;
        __syncthreads();

#pragma unroll
        for (int it = 0; it < 8; ++it) {
            int idx = it * 256 + tid;
            int r = idx >> 5, s = idx & 31;
            float4 v = pre[it];
            __nv_bfloat16 h0 = __float2bfloat16_rn(v.x);
            __nv_bfloat16 h1 = __float2bfloat16_rn(v.y);
            __nv_bfloat16 h2 = __float2bfloat16_rn(v.z);
            __nv_bfloat16 h3 = __float2bfloat16_rn(v.w);
            __nv_bfloat162 ph0 = __halves2bfloat162(h0, h1);
            __nv_bfloat162 ph1 = __halves2bfloat162(h2, h3);
            uint2 uh; uh.x = *(uint32_t*)&ph0; uh.y = *(uint32_t*)&ph1;
            *(uint2*)(Ahi + r * K_PAD + 4 * s) = uh;
            __nv_bfloat162 pl0 = __halves2bfloat162(
                __float2bfloat16_rn(v.x - __bfloat162float(h0)),
                __float2bfloat16_rn(v.y - __bfloat162float(h1)));
            __nv_bfloat162 pl1 = __halves2bfloat162(
                __float2bfloat16_rn(v.z - __bfloat162float(h2)),
                __float2bfloat16_rn(v.w - __bfloat162float(h3)));
            uint2 ul; ul.x = *(uint32_t*)&pl0; ul.y = *(uint32_t*)&pl1;
            *(uint2*)(Alo + r * K_PAD + 4 * s) = ul;
        }
        __syncthreads();

        {
            int tn = t + GRID_GEMM, nrow0 = tn * TILE_M;
#pragma unroll
            for (int it = 0; it < 8; ++it) {
                int idx = it * 256 + tid;
                int r = idx >> 5, s = idx & 31;
                int row = nrow0 + r;
                pre[it] = make_float4(0.f, 0.f, 0.f, 0.f);
                if (tn < ntiles && row < n) pre[it] = X4[(size_t)row * 32 + s];
            }
        }

        float acc[2][4][4];
#pragma unroll
        for (int i = 0; i < 2; i++)
#pragma unroll
            for (int j = 0; j < 4; j++)
#pragma unroll
                for (int q = 0; q < 4; q++) acc[i][j][q] = 0.f;

#pragma unroll
        for (int pass = 0; pass < 3; pass++) {
            uint32_t abase = sb + ((pass == 2) ? SM_ALO : SM_A);
            uint32_t bbase = sb + ((pass == 1) ? SM_BLO : SM_BHI);
            uint32_t arow = abase + (uint32_t)(wm * 32) * (K_PAD * 2) + a_loff;
            uint32_t brow = bbase + (uint32_t)(wn * 32) * (K_PAD * 2) + b_loff;
#pragma unroll
            for (int ks = 0; ks < 8; ks++) {
                uint32_t k0 = ks * 32;
                uint32_t af[2][4], bf[2][4];
#pragma unroll
                for (int mt = 0; mt < 2; mt++)
                    LDMX4(af[mt][0], af[mt][1], af[mt][2], af[mt][3],
                          arow + (uint32_t)(mt * 16) * (K_PAD * 2) + k0);
#pragma unroll
                for (int nt = 0; nt < 2; nt++)
                    LDMX4(bf[nt][0], bf[nt][1], bf[nt][2], bf[nt][3],
                          brow + (uint32_t)(nt * 16) * (K_PAD * 2) + k0);
#pragma unroll
                for (int mt = 0; mt < 2; mt++)
#pragma unroll
                    for (int q = 0; q < 4; q++)
                        mma16816(acc[mt][q], af[mt][0], af[mt][1], af[mt][2], af[mt][3],
                                 bf[q >> 1][(q & 1) * 2], bf[q >> 1][(q & 1) * 2 + 1]);
            }
        }
        __syncthreads();

#pragma unroll
        for (int mt = 0; mt < 2; mt++) {
            int row = wm * 32 + mt * 16 + (l >> 2);
#pragma unroll
            for (int q = 0; q < 4; q++) {
                int col = wn * 32 + q * 8 + 2 * (l & 3);
                *(float2*)(D + row * D_PAD + col) = make_float2(acc[mt][q][0], acc[mt][q][1]);
                *(float2*)(D + (row + 8) * D_PAD + col) = make_float2(acc[mt][q][2], acc[mt][q][3]);
            }
        }
        __syncthreads();

#pragma unroll
        for (int it = 0; it < 8; ++it) {
            int idx = it * 256 + tid;
            int r = idx >> 5, s = idx & 31;
            int row = row0 + r;
            if (row < n) {
                float4 v = *(float4*)(D + r * D_PAD + 4 * s);
                *(float4*)(g_h_node + (size_t)row * H + 4 * s) = v;
            }
        }
        if (tid < 128) {
            int r = tid & 63;
            int row = row0 + r;
            if (row < n) {
                const float* av = (tid < 64) ? a1s : a2s;
                float p = 0.f;
                const float* dr = D + r * D_PAD;
#pragma unroll 8
                for (int c = 0; c < H; c++) p = fmaf(dr[c], av[c], p);
                if (tid < 64) g_s_src[row] = p; else g_s_dst[row] = p;
            }
        }
    }
}

// ====== kgather: score -> top10 -> softmax -> gather -> bf16 hi/lo out ====
#define G_WARPS 8
__global__ void __launch_bounds__(256) kgather(const int* __restrict__ src,
                                               const int* __restrict__ rid, int n) {
    __shared__ float ats[G_WARPS][16];
    __shared__ int   sks[G_WARPS][16];
    __shared__ int   rks[G_WARPS][16];
    int tid = threadIdx.x;
    int w = tid >> 5, l = tid & 31;
    int node = blockIdx.x * G_WARPS + w;
    if (node >= n) return;

    float sdst = g_s_dst[node];
    int s = src[node * DEG + l];
    int r = rid[node * DEG + l];
    float v = (g_s_src[s] + sdst) + g_s_rel[r];
    float sc = (v >= 0.f) ? v : 0.2f * v;

    int rank = 0;
#pragma unroll
    for (int j = 0; j < DEG; j++) {
        float vj = __shfl_sync(0xffffffffu, sc, j);
        rank += (vj > sc) || (vj == sc && j < l);
    }
    bool sel = (rank < TOPK);

    float m = sel ? sc : __int_as_float(0xff800000);
#pragma unroll
    for (int off = 16; off; off >>= 1) m = fmaxf(m, __shfl_xor_sync(0xffffffffu, m, off));
    float e = sel ? expf(sc - m) : 0.f;
    float z = e;
#pragma unroll
    for (int off = 16; off; off >>= 1) z += __shfl_xor_sync(0xffffffffu, z, off);
    float attn = e / z;

    if (sel) { ats[w][rank] = attn; sks[w][rank] = s; rks[w][rank] = r; }
    __syncwarp();

    float4 acc = make_float4(0.f, 0.f, 0.f, 0.f);
#pragma unroll
    for (int k = 0; k < TOPK; k++) {
        int sk = sks[w][k], rk = rks[w][k];
        float ak = ats[w][k];
        // h_node gather: L2-only (no L1 reuse across 76.8MB working set)
        float4 hn = __ldcg((const float4*)(g_h_node + (size_t)sk * H + 4 * l));
        float4 hr = *(const float4*)(g_h_rel + rk * H + 4 * l);
        acc.x = fmaf(ak, hn.x + hr.x, acc.x);
        acc.y = fmaf(ak, hn.y + hr.y, acc.y);
        acc.z = fmaf(ak, hn.z + hr.z, acc.z);
        acc.w = fmaf(ak, hn.w + hr.w, acc.w);
    }

    // split to bf16 hi/lo here (bit-identical to splitting in kgemm1)
    __nv_bfloat16 h0 = __float2bfloat16_rn(acc.x);
    __nv_bfloat16 h1 = __float2bfloat16_rn(acc.y);
    __nv_bfloat16 h2 = __float2bfloat16_rn(acc.z);
    __nv_bfloat16 h3 = __float2bfloat16_rn(acc.w);
    __nv_bfloat162 ph0 = __halves2bfloat162(h0, h1);
    __nv_bfloat162 ph1 = __halves2bfloat162(h2, h3);
    uint2 uh; uh.x = *(uint32_t*)&ph0; uh.y = *(uint32_t*)&ph1;
    *(uint2*)(g_nA_hi + (size_t)node * H + 4 * l) = uh;
    __nv_bfloat162 pl0 = __halves2bfloat162(
        __float2bfloat16_rn(acc.x - __bfloat162float(h0)),
        __float2bfloat16_rn(acc.y - __bfloat162float(h1)));
    __nv_bfloat162 pl1 = __halves2bfloat162(
        __float2bfloat16_rn(acc.z - __bfloat162float(h2)),
        __float2bfloat16_rn(acc.w - __bfloat162float(h3)));
    uint2 ul; ul.x = *(uint32_t*)&pl0; ul.y = *(uint32_t*)&pl1;
    *(uint2*)(g_nA_lo + (size_t)node * H + 4 * l) = ul;
}

// ====== kgemm1: out = tanh(neigh @ neigh_w); A pre-split, pure copy =======
__global__ void __launch_bounds__(256, 2) kgemm1(const float* __restrict__ NW,
                                                 float* __restrict__ out,
                                                 int n, int ntiles) {
    extern __shared__ char sm[];
    uint32_t sb = smem_u32(sm);
    float* D = (float*)(sm + SM_A);
    __nv_bfloat16* Ahi = (__nv_bfloat16*)(sm + SM_A);
    __nv_bfloat16* Alo = (__nv_bfloat16*)(sm + SM_ALO);
    int tid = threadIdx.x;
    int w = tid >> 5, l = tid & 31;
    int wm = w >> 2, wn = w & 3;
    int quad = l >> 3, lrow = l & 7;

    // ---- stage B once (convert NW inline) ----
    stage_B_from(NW, (__nv_bfloat16*)(sm + SM_BHI), (__nv_bfloat16*)(sm + SM_BLO), tid);

    uint32_t a_loff = (uint32_t)(((lrow + (quad & 1) * 8) * K_PAD + (quad >> 1) * 8) * 2);
    uint32_t b_loff = (uint32_t)(((lrow + (quad >> 1) * 8) * K_PAD + (quad & 1) * 8) * 2);

    for (int t = blockIdx.x; t < ntiles; t += GRID_GEMM) {
        int row0 = t * TILE_M;
        __syncthreads();                 // prev D reads done / B ready

        // ---- stage A: straight uint4 copy of pre-split bf16 (no convert) --
        {
            const uint4* nh = (const uint4*)(g_nA_hi + (size_t)row0 * H);
            const uint4* nl = (const uint4*)(g_nA_lo + (size_t)row0 * H);
#pragma unroll
            for (int it = 0; it < 4; ++it) {
                int idx = it * 256 + tid;    // 1024 uint4 per buffer
                int r = idx >> 4, s = idx & 15;
                uint4 vh = nh[idx];
                uint4 vl = nl[idx];
                *(uint4*)(Ahi + r * K_PAD + 8 * s) = vh;
                *(uint4*)(Alo + r * K_PAD + 8 * s) = vl;
            }
        }
        __syncthreads();

        float acc[2][4][4];
#pragma unroll
        for (int i = 0; i < 2; i++)
#pragma unroll
            for (int j = 0; j < 4; j++)
#pragma unroll
                for (int q = 0; q < 4; q++) acc[i][j][q] = 0.f;

#pragma unroll
        for (int pass = 0; pass < 3; pass++) {
            uint32_t abase = sb + ((pass == 2) ? SM_ALO : SM_A);
            uint32_t bbase = sb + ((pass == 1) ? SM_BLO : SM_BHI);
            uint32_t arow = abase + (uint32_t)(wm * 32) * (K_PAD * 2) + a_loff;
            uint32_t brow = bbase + (uint32_t)(wn * 32) * (K_PAD * 2) + b_loff;
#pragma unroll
            for (int ks = 0; ks < 8; ks++) {
                uint32_t k0 = ks * 32;
                uint32_t af[2][4], bf[2][4];
#pragma unroll
                for (int mt = 0; mt < 2; mt++)
                    LDMX4(af[mt][0], af[mt][1], af[mt][2], af[mt][3],
                          arow + (uint32_t)(mt * 16) * (K_PAD * 2) + k0);
#pragma unroll
                for (int nt = 0; nt < 2; nt++)
                    LDMX4(bf[nt][0], bf[nt][1], bf[nt][2], bf[nt][3],
                          brow + (uint32_t)(nt * 16) * (K_PAD * 2) + k0);
#pragma unroll
                for (int mt = 0; mt < 2; mt++)
#pragma unroll
                    for (int q = 0; q < 4; q++)
                        mma16816(acc[mt][q], af[mt][0], af[mt][1], af[mt][2], af[mt][3],
                                 bf[q >> 1][(q & 1) * 2], bf[q >> 1][(q & 1) * 2 + 1]);
            }
        }
        __syncthreads();

#pragma unroll
        for (int mt = 0; mt < 2; mt++) {
            int row = wm * 32 + mt * 16 + (l >> 2);
#pragma unroll
            for (int q = 0; q < 4; q++) {
                int col = wn * 32 + q * 8 + 2 * (l & 3);
                *(float2*)(D + row * D_PAD + col) = make_float2(acc[mt][q][0], acc[mt][q][1]);
                *(float2*)(D + (row + 8) * D_PAD + col) = make_float2(acc[mt][q][2], acc[mt][q][3]);
            }
        }
        __syncthreads();

        // ---- tanh epilogue ----
#pragma unroll
        for (int it = 0; it < 8; ++it) {
            int idx = it * 256 + tid;
            int r = idx >> 5, s = idx & 31;
            int row = row0 + r;
            if (row < n) {
                float4 v = *(float4*)(D + r * D_PAD + 4 * s);
                *(float4*)(out + (size_t)row * H + 4 * s) =
                    make_float4(tanhf(v.x), tanhf(v.y), tanhf(v.z), tanhf(v.w));
            }
        }
    }
}

// ============================== launch =====================================
extern "C" void kernel_launch(void* const* d_in, const int* in_sizes, int n_in,
                              void* d_out, int out_size) {
    const float* ent = (const float*)d_in[0];
    const float* rel = (const float*)d_in[1];
    const float* W   = (const float*)d_in[2];
    const float* W_r = (const float*)d_in[3];
    const float* a   = (const float*)d_in[4];
    const float* nw  = (const float*)d_in[5];
    const int*   src = (const int*)d_in[6];
    const int*   rid = (const int*)d_in[7];
    float* out = (float*)d_out;

    int n    = in_sizes[0] / H;   // 150000
    int nrel = in_sizes[1] / H;   // 500
    int ntiles = (n + TILE_M - 1) / TILE_M;

    cudaFuncSetAttribute(kgemm0, cudaFuncAttributeMaxDynamicSharedMemorySize, SM_TOTAL);
    cudaFuncSetAttribute(kgemm1, cudaFuncAttributeMaxDynamicSharedMemorySize, SM_TOTAL);

    kgemm0<<<GRID_GEMM, 256, SM_TOTAL>>>(ent, a, rel, W_r, W, n, ntiles, nrel);
    kgather<<<(n + G_WARPS - 1) / G_WARPS, 256>>>(src, rid, n);
    kgemm1<<<GRID_GEMM, 256, SM_TOTAL>>>(nw, out, n, ntiles);
}

// round 13
// speedup vs baseline: 1.3398x; 1.0190x over previous
#include <cuda_runtime.h>
#include <cuda_bf16.h>
#include <math.h>
#include <stdint.h>

#define N_ENT_MAX 150016
#define H 128
#define DEG 32
#define TOPK 10
#define TILE_M 64
#define K_PAD 136     // bf16 elems per smem row (272B) -> conflict-free ldmatrix
#define D_PAD 132     // f32 elems per D smem row

// -------- device scratch (no allocs allowed) --------
__device__ float g_h_node[N_ENT_MAX * H];
__device__ float g_s_src[N_ENT_MAX];
__device__ float g_s_dst[N_ENT_MAX];
__device__ float g_h_rel[512 * H];
__device__ float g_s_rel[512];
// Pre-transposed B operands: B[n][k] = Wmat[k][n], bf16 hi/lo, rows padded to K_PAD
__device__ __align__(16) __nv_bfloat16 g_BW_hi[H * K_PAD];
__device__ __align__(16) __nv_bfloat16 g_BW_lo[H * K_PAD];
__device__ __align__(16) __nv_bfloat16 g_BN_hi[H * K_PAD];
__device__ __align__(16) __nv_bfloat16 g_BN_lo[H * K_PAD];
// neigh, pre-split to bf16 hi/lo by kgather (identical values to a later split)
__device__ __align__(16) __nv_bfloat16 g_nA_hi[N_ENT_MAX * H];
__device__ __align__(16) __nv_bfloat16 g_nA_lo[N_ENT_MAX * H];

// ---------------- helpers ---------------------------
__device__ __forceinline__ uint32_t smem_u32(const void* p) {
    uint32_t a;
    asm("{ .reg .u64 t; cvta.to.shared.u64 t, %1; cvt.u32.u64 %0, t; }"
        : "=r"(a) : "l"(p));
    return a;
}

#define LDMX4(r0, r1, r2, r3, addr)                                             \
    asm volatile("ldmatrix.sync.aligned.m8n8.x4.shared.b16 {%0,%1,%2,%3}, [%4];"\
                 : "=r"(r0), "=r"(r1), "=r"(r2), "=r"(r3) : "r"(addr))

__device__ __forceinline__ void mma16816(float* c, uint32_t a0, uint32_t a1,
                                         uint32_t a2, uint32_t a3,
                                         uint32_t b0, uint32_t b1) {
    asm volatile(
        "mma.sync.aligned.m16n8k16.row.col.f32.bf16.bf16.f32 "
        "{%0,%1,%2,%3}, {%4,%5,%6,%7}, {%8,%9}, {%0,%1,%2,%3};"
        : "+f"(c[0]), "+f"(c[1]), "+f"(c[2]), "+f"(c[3])
        : "r"(a0), "r"(a1), "r"(a2), "r"(a3), "r"(b0), "r"(b1));
}

// ============ prep: B[n][k] = src[k][n] as bf16 hi/lo ======================
__global__ void kprepB(const float* __restrict__ W, const float* __restrict__ NW) {
    int tid = blockIdx.x * blockDim.x + threadIdx.x;
    if (tid >= H * H) return;
    int k = tid >> 7, nn = tid & 127;
    int off = nn * K_PAD + k;
    {
        float f = W[tid];
        __nv_bfloat16 hi = __float2bfloat16_rn(f);
        g_BW_hi[off] = hi;
        g_BW_lo[off] = __float2bfloat16_rn(f - __bfloat162float(hi));
    }
    {
        float f = NW[tid];
        __nv_bfloat16 hi = __float2bfloat16_rn(f);
        g_BN_hi[off] = hi;
        g_BN_lo[off] = __float2bfloat16_rn(f - __bfloat162float(hi));
    }
}

// -------- shared smem layout for both GEMM kernels --------
#define SM_BHI 0
#define SM_BLO 34816
#define SM_A   69632
#define SM_ALO 87040
#define SM_A1  104448
#define SM_A2  104960
#define SM_TOTAL 106496
#define GRID_GEMM 296       // 148 SMs x 2

// ====== kgemm0: h_node = ent_emb @ W + s_src/s_dst (+inline krel) =========
// (identical to the R10 champion's MODE 0 path)
__global__ void __launch_bounds__(256) kgemm0(const float* __restrict__ Xin,
                                              const float* __restrict__ avec,
                                              const float* __restrict__ rel_emb,
                                              const float* __restrict__ W_r,
                                              int n, int ntiles, int nrel) {
    extern __shared__ char sm[];
    uint32_t sb = smem_u32(sm);
    float* a1s = (float*)(sm + SM_A1);
    float* a2s = (float*)(sm + SM_A2);
    float* D = (float*)(sm + SM_A);
    __nv_bfloat16* Ahi = (__nv_bfloat16*)(sm + SM_A);
    __nv_bfloat16* Alo = (__nv_bfloat16*)(sm + SM_ALO);
    int tid = threadIdx.x;
    int w = tid >> 5, l = tid & 31;
    int wm = w >> 2, wn = w & 3;
    int quad = l >> 3, lrow = l & 7;

    if (tid < 128) { a1s[tid] = avec[tid]; a2s[tid] = avec[H + tid]; }

    // ---- inline krel: blocks 0..(nrel+1)/2-1 handle 2 relations each ----
    if (blockIdx.x < (nrel + 1) / 2) {
        int rr = blockIdx.x * 2 + (tid >> 7);
        int j = tid & 127;
        if (rr < nrel) {
            const float* x = rel_emb + rr * H;
            float acc = 0.f;
#pragma unroll 8
            for (int h = 0; h < H; ++h) acc = fmaf(x[h], W_r[h * H + j], acc);
            g_h_rel[rr * H + j] = acc;
            float p = acc * avec[2 * H + j];
#pragma unroll
            for (int off = 16; off; off >>= 1) p += __shfl_xor_sync(0xffffffffu, p, off);
            if ((tid & 31) == 0) D[tid >> 5] = p;
        }
        __syncthreads();
        if ((tid & 127) == 0 && rr < nrel) {
            int b = (tid >> 7) * 4;
            g_s_rel[rr] = D[b] + D[b + 1] + D[b + 2] + D[b + 3];
        }
    }

    // ---- stage B once (uint4 copy of pre-converted arrays) ----
    {
        const uint4* bh = (const uint4*)(const void*)g_BW_hi;
        const uint4* bl = (const uint4*)(const void*)g_BW_lo;
        uint4* dh = (uint4*)(sm + SM_BHI);
        uint4* dl = (uint4*)(sm + SM_BLO);
        for (int i = tid; i < (H * K_PAD * 2) / 16; i += 256) { dh[i] = bh[i]; dl[i] = bl[i]; }
    }

    const float4* X4 = (const float4*)Xin;
    uint32_t a_loff = (uint32_t)(((lrow + (quad & 1) * 8) * K_PAD + (quad >> 1) * 8) * 2);
    uint32_t b_loff = (uint32_t)(((lrow + (quad >> 1) * 8) * K_PAD + (quad & 1) * 8) * 2);

    float4 pre[8];
    {
        int t0 = blockIdx.x, row0 = t0 * TILE_M;
#pragma unroll
        for (int it = 0; it < 8; ++it) {
            int idx = it * 256 + tid;
            int r = idx >> 5, s = idx & 31;
            int row = row0 + r;
            pre[it] = make_float4(0.f, 0.f, 0.f, 0.f);
            if (t0 < ntiles && row < n) pre[it] = X4[(size_t)row * 32 + s];
        }
    }

    for (int t = blockIdx.x; t < ntiles; t += GRID_GEMM) {
        int row0 = t * TILE_M;
        __syncthreads();

#pragma unroll
        for (int it = 0; it < 8; ++it) {
            int idx = it * 256 + tid;
            int r = idx >> 5, s = idx & 31;
            float4 v = pre[it];
            __nv_bfloat16 h0 = __float2bfloat16_rn(v.x);
            __nv_bfloat16 h1 = __float2bfloat16_rn(v.y);
            __nv_bfloat16 h2 = __float2bfloat16_rn(v.z);
            __nv_bfloat16 h3 = __float2bfloat16_rn(v.w);
            __nv_bfloat162 ph0 = __halves2bfloat162(h0, h1);
            __nv_bfloat162 ph1 = __halves2bfloat162(h2, h3);
            uint2 uh; uh.x = *(uint32_t*)&ph0; uh.y = *(uint32_t*)&ph1;
            *(uint2*)(Ahi + r * K_PAD + 4 * s) = uh;
            __nv_bfloat162 pl0 = __halves2bfloat162(
                __float2bfloat16_rn(v.x - __bfloat162float(h0)),
                __float2bfloat16_rn(v.y - __bfloat162float(h1)));
            __nv_bfloat162 pl1 = __halves2bfloat162(
                __float2bfloat16_rn(v.z - __bfloat162float(h2)),
                __float2bfloat16_rn(v.w - __bfloat162float(h3)));
            uint2 ul; ul.x = *(uint32_t*)&pl0; ul.y = *(uint32_t*)&pl1;
            *(uint2*)(Alo + r * K_PAD + 4 * s) = ul;
        }
        __syncthreads();

        {
            int tn = t + GRID_GEMM, nrow0 = tn * TILE_M;
#pragma unroll
            for (int it = 0; it < 8; ++it) {
                int idx = it * 256 + tid;
                int r = idx >> 5, s = idx & 31;
                int row = nrow0 + r;
                pre[it] = make_float4(0.f, 0.f, 0.f, 0.f);
                if (tn < ntiles && row < n) pre[it] = X4[(size_t)row * 32 + s];
            }
        }

        float acc[2][4][4];
#pragma unroll
        for (int i = 0; i < 2; i++)
#pragma unroll
            for (int j = 0; j < 4; j++)
#pragma unroll
                for (int q = 0; q < 4; q++) acc[i][j][q] = 0.f;

#pragma unroll
        for (int pass = 0; pass < 3; pass++) {
            uint32_t abase = sb + ((pass == 2) ? SM_ALO : SM_A);
            uint32_t bbase = sb + ((pass == 1) ? SM_BLO : SM_BHI);
            uint32_t arow = abase + (uint32_t)(wm * 32) * (K_PAD * 2) + a_loff;
            uint32_t brow = bbase + (uint32_t)(wn * 32) * (K_PAD * 2) + b_loff;
#pragma unroll
            for (int ks = 0; ks < 8; ks++) {
                uint32_t k0 = ks * 32;
                uint32_t af[2][4], bf[2][4];
#pragma unroll
                for (int mt = 0; mt < 2; mt++)
                    LDMX4(af[mt][0], af[mt][1], af[mt][2], af[mt][3],
                          arow + (uint32_t)(mt * 16) * (K_PAD * 2) + k0);
#pragma unroll
                for (int nt = 0; nt < 2; nt++)
                    LDMX4(bf[nt][0], bf[nt][1], bf[nt][2], bf[nt][3],
                          brow + (uint32_t)(nt * 16) * (K_PAD * 2) + k0);
#pragma unroll
                for (int mt = 0; mt < 2; mt++)
#pragma unroll
                    for (int q = 0; q < 4; q++)
                        mma16816(acc[mt][q], af[mt][0], af[mt][1], af[mt][2], af[mt][3],
                                 bf[q >> 1][(q & 1) * 2], bf[q >> 1][(q & 1) * 2 + 1]);
            }
        }
        __syncthreads();

#pragma unroll
        for (int mt = 0; mt < 2; mt++) {
            int row = wm * 32 + mt * 16 + (l >> 2);
#pragma unroll
            for (int q = 0; q < 4; q++) {
                int col = wn * 32 + q * 8 + 2 * (l & 3);
                *(float2*)(D + row * D_PAD + col) = make_float2(acc[mt][q][0], acc[mt][q][1]);
                *(float2*)(D + (row + 8) * D_PAD + col) = make_float2(acc[mt][q][2], acc[mt][q][3]);
            }
        }
        __syncthreads();

#pragma unroll
        for (int it = 0; it < 8; ++it) {
            int idx = it * 256 + tid;
            int r = idx >> 5, s = idx & 31;
            int row = row0 + r;
            if (row < n) {
                float4 v = *(float4*)(D + r * D_PAD + 4 * s);
                *(float4*)(g_h_node + (size_t)row * H + 4 * s) = v;
            }
        }
        if (tid < 128) {
            int r = tid & 63;
            int row = row0 + r;
            if (row < n) {
                const float* av = (tid < 64) ? a1s : a2s;
                float p = 0.f;
                const float* dr = D + r * D_PAD;
#pragma unroll 8
                for (int c = 0; c < H; c++) p = fmaf(dr[c], av[c], p);
                if (tid < 64) g_s_src[row] = p; else g_s_dst[row] = p;
            }
        }
    }
}

// ====== kgather: score -> top10 -> softmax -> gather -> bf16 hi/lo out ====
#define G_WARPS 8
__global__ void __launch_bounds__(256) kgather(const int* __restrict__ src,
                                               const int* __restrict__ rid, int n) {
    __shared__ float ats[G_WARPS][16];
    __shared__ int   sks[G_WARPS][16];
    __shared__ int   rks[G_WARPS][16];
    int tid = threadIdx.x;
    int w = tid >> 5, l = tid & 31;
    int node = blockIdx.x * G_WARPS + w;
    if (node >= n) return;

    float sdst = g_s_dst[node];
    int s = src[node * DEG + l];
    int r = rid[node * DEG + l];
    float v = (g_s_src[s] + sdst) + g_s_rel[r];
    float sc = (v >= 0.f) ? v : 0.2f * v;

    int rank = 0;
#pragma unroll
    for (int j = 0; j < DEG; j++) {
        float vj = __shfl_sync(0xffffffffu, sc, j);
        rank += (vj > sc) || (vj == sc && j < l);
    }
    bool sel = (rank < TOPK);

    float m = sel ? sc : __int_as_float(0xff800000);
#pragma unroll
    for (int off = 16; off; off >>= 1) m = fmaxf(m, __shfl_xor_sync(0xffffffffu, m, off));
    float e = sel ? expf(sc - m) : 0.f;
    float z = e;
#pragma unroll
    for (int off = 16; off; off >>= 1) z += __shfl_xor_sync(0xffffffffu, z, off);
    float attn = e / z;

    if (sel) { ats[w][rank] = attn; sks[w][rank] = s; rks[w][rank] = r; }
    __syncwarp();

    float4 acc = make_float4(0.f, 0.f, 0.f, 0.f);
#pragma unroll
    for (int k = 0; k < TOPK; k++) {
        int sk = sks[w][k], rk = rks[w][k];
        float ak = ats[w][k];
        // h_node gather: L2-only (no L1 reuse across 76.8MB working set)
        float4 hn = __ldcg((const float4*)(g_h_node + (size_t)sk * H + 4 * l));
        float4 hr = *(const float4*)(g_h_rel + rk * H + 4 * l);
        acc.x = fmaf(ak, hn.x + hr.x, acc.x);
        acc.y = fmaf(ak, hn.y + hr.y, acc.y);
        acc.z = fmaf(ak, hn.z + hr.z, acc.z);
        acc.w = fmaf(ak, hn.w + hr.w, acc.w);
    }

    // split to bf16 hi/lo here (bit-identical to splitting in kgemm1)
    __nv_bfloat16 h0 = __float2bfloat16_rn(acc.x);
    __nv_bfloat16 h1 = __float2bfloat16_rn(acc.y);
    __nv_bfloat16 h2 = __float2bfloat16_rn(acc.z);
    __nv_bfloat16 h3 = __float2bfloat16_rn(acc.w);
    __nv_bfloat162 ph0 = __halves2bfloat162(h0, h1);
    __nv_bfloat162 ph1 = __halves2bfloat162(h2, h3);
    uint2 uh; uh.x = *(uint32_t*)&ph0; uh.y = *(uint32_t*)&ph1;
    *(uint2*)(g_nA_hi + (size_t)node * H + 4 * l) = uh;
    __nv_bfloat162 pl0 = __halves2bfloat162(
        __float2bfloat16_rn(acc.x - __bfloat162float(h0)),
        __float2bfloat16_rn(acc.y - __bfloat162float(h1)));
    __nv_bfloat162 pl1 = __halves2bfloat162(
        __float2bfloat16_rn(acc.z - __bfloat162float(h2)),
        __float2bfloat16_rn(acc.w - __bfloat162float(h3)));
    uint2 ul; ul.x = *(uint32_t*)&pl0; ul.y = *(uint32_t*)&pl1;
    *(uint2*)(g_nA_lo + (size_t)node * H + 4 * l) = ul;
}

// ====== kgemm1: out = tanh(neigh @ neigh_w); A pre-split, pure copies =====
__global__ void __launch_bounds__(256, 2) kgemm1(float* __restrict__ out,
                                                 int n, int ntiles) {
    extern __shared__ char sm[];
    uint32_t sb = smem_u32(sm);
    float* D = (float*)(sm + SM_A);
    __nv_bfloat16* Ahi = (__nv_bfloat16*)(sm + SM_A);
    __nv_bfloat16* Alo = (__nv_bfloat16*)(sm + SM_ALO);
    int tid = threadIdx.x;
    int w = tid >> 5, l = tid & 31;
    int wm = w >> 2, wn = w & 3;
    int quad = l >> 3, lrow = l & 7;

    // ---- stage B once (uint4 copy of pre-converted arrays) ----
    {
        const uint4* bh = (const uint4*)(const void*)g_BN_hi;
        const uint4* bl = (const uint4*)(const void*)g_BN_lo;
        uint4* dh = (uint4*)(sm + SM_BHI);
        uint4* dl = (uint4*)(sm + SM_BLO);
        for (int i = tid; i < (H * K_PAD * 2) / 16; i += 256) { dh[i] = bh[i]; dl[i] = bl[i]; }
    }

    uint32_t a_loff = (uint32_t)(((lrow + (quad & 1) * 8) * K_PAD + (quad >> 1) * 8) * 2);
    uint32_t b_loff = (uint32_t)(((lrow + (quad >> 1) * 8) * K_PAD + (quad & 1) * 8) * 2);

    for (int t = blockIdx.x; t < ntiles; t += GRID_GEMM) {
        int row0 = t * TILE_M;
        __syncthreads();                 // prev D reads done / B ready

        // ---- stage A: straight uint4 copy of pre-split bf16 (no convert) --
        {
            const uint4* nh = (const uint4*)(g_nA_hi + (size_t)row0 * H);
            const uint4* nl = (const uint4*)(g_nA_lo + (size_t)row0 * H);
#pragma unroll
            for (int it = 0; it < 4; ++it) {
                int idx = it * 256 + tid;    // 1024 uint4 per buffer
                int r = idx >> 4, s = idx & 15;
                uint4 vh = nh[idx];
                uint4 vl = nl[idx];
                *(uint4*)(Ahi + r * K_PAD + 8 * s) = vh;
                *(uint4*)(Alo + r * K_PAD + 8 * s) = vl;
            }
        }
        __syncthreads();

        float acc[2][4][4];
#pragma unroll
        for (int i = 0; i < 2; i++)
#pragma unroll
            for (int j = 0; j < 4; j++)
#pragma unroll
                for (int q = 0; q < 4; q++) acc[i][j][q] = 0.f;

#pragma unroll
        for (int pass = 0; pass < 3; pass++) {
            uint32_t abase = sb + ((pass == 2) ? SM_ALO : SM_A);
            uint32_t bbase = sb + ((pass == 1) ? SM_BLO : SM_BHI);
            uint32_t arow = abase + (uint32_t)(wm * 32) * (K_PAD * 2) + a_loff;
            uint32_t brow = bbase + (uint32_t)(wn * 32) * (K_PAD * 2) + b_loff;
#pragma unroll
            for (int ks = 0; ks < 8; ks++) {
                uint32_t k0 = ks * 32;
                uint32_t af[2][4], bf[2][4];
#pragma unroll
                for (int mt = 0; mt < 2; mt++)
                    LDMX4(af[mt][0], af[mt][1], af[mt][2], af[mt][3],
                          arow + (uint32_t)(mt * 16) * (K_PAD * 2) + k0);
#pragma unroll
                for (int nt = 0; nt < 2; nt++)
                    LDMX4(bf[nt][0], bf[nt][1], bf[nt][2], bf[nt][3],
                          brow + (uint32_t)(nt * 16) * (K_PAD * 2) + k0);
#pragma unroll
                for (int mt = 0; mt < 2; mt++)
#pragma unroll
                    for (int q = 0; q < 4; q++)
                        mma16816(acc[mt][q], af[mt][0], af[mt][1], af[mt][2], af[mt][3],
                                 bf[q >> 1][(q & 1) * 2], bf[q >> 1][(q & 1) * 2 + 1]);
            }
        }
        __syncthreads();

#pragma unroll
        for (int mt = 0; mt < 2; mt++) {
            int row = wm * 32 + mt * 16 + (l >> 2);
#pragma unroll
            for (int q = 0; q < 4; q++) {
                int col = wn * 32 + q * 8 + 2 * (l & 3);
                *(float2*)(D + row * D_PAD + col) = make_float2(acc[mt][q][0], acc[mt][q][1]);
                *(float2*)(D + (row + 8) * D_PAD + col) = make_float2(acc[mt][q][2], acc[mt][q][3]);
            }
        }
        __syncthreads();

        // ---- tanh epilogue ----
#pragma unroll
        for (int it = 0; it < 8; ++it) {
            int idx = it * 256 + tid;
            int r = idx >> 5, s = idx & 31;
            int row = row0 + r;
            if (row < n) {
                float4 v = *(float4*)(D + r * D_PAD + 4 * s);
                *(float4*)(out + (size_t)row * H + 4 * s) =
                    make_float4(tanhf(v.x), tanhf(v.y), tanhf(v.z), tanhf(v.w));
            }
        }
    }
}

// ============================== launch =====================================
extern "C" void kernel_launch(void* const* d_in, const int* in_sizes, int n_in,
                              void* d_out, int out_size) {
    const float* ent = (const float*)d_in[0];
    const float* rel = (const float*)d_in[1];
    const float* W   = (const float*)d_in[2];
    const float* W_r = (const float*)d_in[3];
    const float* a   = (const float*)d_in[4];
    const float* nw  = (const float*)d_in[5];
    const int*   src = (const int*)d_in[6];
    const int*   rid = (const int*)d_in[7];
    float* out = (float*)d_out;

    int n    = in_sizes[0] / H;   // 150000
    int nrel = in_sizes[1] / H;   // 500
    int ntiles = (n + TILE_M - 1) / TILE_M;

    cudaFuncSetAttribute(kgemm0, cudaFuncAttributeMaxDynamicSharedMemorySize, SM_TOTAL);
    cudaFuncSetAttribute(kgemm1, cudaFuncAttributeMaxDynamicSharedMemorySize, SM_TOTAL);

    kprepB<<<(H * H + 255) / 256, 256>>>(W, nw);
    kgemm0<<<GRID_GEMM, 256, SM_TOTAL>>>(ent, a, rel, W_r, n, ntiles, nrel);
    kgather<<<(n + G_WARPS - 1) / G_WARPS, 256>>>(src, rid, n);
    kgemm1<<<GRID_GEMM, 256, SM_TOTAL>>>(out, n, ntiles);
}

// round 14
// speedup vs baseline: 1.4178x; 1.0582x over previous
#include <cuda_runtime.h>
#include <cuda_bf16.h>
#include <math.h>
#include <stdint.h>

#define N_ENT_MAX 150016
#define H 128
#define DEG 32
#define TOPK 10
#define TILE_M 64
#define K_PAD 136     // bf16 elems per smem row (272B) -> conflict-free ldmatrix
#define D_PAD 132     // f32 elems per D smem row

// -------- device scratch (no allocs allowed) --------
__device__ float g_h_node[N_ENT_MAX * H];
__device__ float g_s_src[N_ENT_MAX];
__device__ float g_s_dst[N_ENT_MAX];
__device__ float g_h_rel[512 * H];
__device__ float g_s_rel[512];
// Pre-transposed B operands: B[n][k] = Wmat[k][n], bf16 hi/lo, rows padded to K_PAD
__device__ __align__(16) __nv_bfloat16 g_BW_hi[H * K_PAD];
__device__ __align__(16) __nv_bfloat16 g_BW_lo[H * K_PAD];
__device__ __align__(16) __nv_bfloat16 g_BN_hi[H * K_PAD];
__device__ __align__(16) __nv_bfloat16 g_BN_lo[H * K_PAD];
// neigh, pre-split to bf16 hi/lo by kgather (identical values to a later split)
__device__ __align__(16) __nv_bfloat16 g_nA_hi[N_ENT_MAX * H];
__device__ __align__(16) __nv_bfloat16 g_nA_lo[N_ENT_MAX * H];

// ---------------- helpers ---------------------------
__device__ __forceinline__ uint32_t smem_u32(const void* p) {
    uint32_t a;
    asm("{ .reg .u64 t; cvta.to.shared.u64 t, %1; cvt.u32.u64 %0, t; }"
        : "=r"(a) : "l"(p));
    return a;
}

#define LDMX4(r0, r1, r2, r3, addr)                                             \
    asm volatile("ldmatrix.sync.aligned.m8n8.x4.shared.b16 {%0,%1,%2,%3}, [%4];"\
                 : "=r"(r0), "=r"(r1), "=r"(r2), "=r"(r3) : "r"(addr))

#define CPASYNC16(dst, src)                                                     \
    asm volatile("cp.async.cg.shared.global [%0], [%1], 16;"                    \
                 :: "r"(dst), "l"(src))
#define CPASYNC_COMMIT() asm volatile("cp.async.commit_group;" ::: "memory")
#define CPASYNC_WAIT0()  asm volatile("cp.async.wait_group 0;" ::: "memory")

__device__ __forceinline__ void mma16816(float* c, uint32_t a0, uint32_t a1,
                                         uint32_t a2, uint32_t a3,
                                         uint32_t b0, uint32_t b1) {
    asm volatile(
        "mma.sync.aligned.m16n8k16.row.col.f32.bf16.bf16.f32 "
        "{%0,%1,%2,%3}, {%4,%5,%6,%7}, {%8,%9}, {%0,%1,%2,%3};"
        : "+f"(c[0]), "+f"(c[1]), "+f"(c[2]), "+f"(c[3])
        : "r"(a0), "r"(a1), "r"(a2), "r"(a3), "r"(b0), "r"(b1));
}

// ============ prep: B[n][k] = src[k][n] as bf16 hi/lo ======================
__global__ void kprepB(const float* __restrict__ W, const float* __restrict__ NW) {
    int tid = blockIdx.x * blockDim.x + threadIdx.x;
    if (tid >= H * H) return;
    int k = tid >> 7, nn = tid & 127;
    int off = nn * K_PAD + k;
    {
        float f = W[tid];
        __nv_bfloat16 hi = __float2bfloat16_rn(f);
        g_BW_hi[off] = hi;
        g_BW_lo[off] = __float2bfloat16_rn(f - __bfloat162float(hi));
    }
    {
        float f = NW[tid];
        __nv_bfloat16 hi = __float2bfloat16_rn(f);
        g_BN_hi[off] = hi;
        g_BN_lo[off] = __float2bfloat16_rn(f - __bfloat162float(hi));
    }
}

// -------- shared smem layout for both GEMM kernels --------
#define SM_BHI 0
#define SM_BLO 34816
#define SM_A   69632
#define SM_ALO 87040
#define SM_A1  104448
#define SM_A2  104960
#define SM_TOTAL 106496
#define GRID_GEMM 296       // 148 SMs x 2

// ====== kgemm0: h_node = ent_emb @ W + s_src/s_dst (+inline krel) =========
// (byte-identical to the R10 champion's MODE 0 path)
__global__ void __launch_bounds__(256) kgemm0(const float* __restrict__ Xin,
                                              const float* __restrict__ avec,
                                              const float* __restrict__ rel_emb,
                                              const float* __restrict__ W_r,
                                              int n, int ntiles, int nrel) {
    extern __shared__ char sm[];
    uint32_t sb = smem_u32(sm);
    float* a1s = (float*)(sm + SM_A1);
    float* a2s = (float*)(sm + SM_A2);
    float* D = (float*)(sm + SM_A);
    __nv_bfloat16* Ahi = (__nv_bfloat16*)(sm + SM_A);
    __nv_bfloat16* Alo = (__nv_bfloat16*)(sm + SM_ALO);
    int tid = threadIdx.x;
    int w = tid >> 5, l = tid & 31;
    int wm = w >> 2, wn = w & 3;
    int quad = l >> 3, lrow = l & 7;

    if (tid < 128) { a1s[tid] = avec[tid]; a2s[tid] = avec[H + tid]; }

    // ---- inline krel: blocks 0..(nrel+1)/2-1 handle 2 relations each ----
    if (blockIdx.x < (nrel + 1) / 2) {
        int rr = blockIdx.x * 2 + (tid >> 7);
        int j = tid & 127;
        if (rr < nrel) {
            const float* x = rel_emb + rr * H;
            float acc = 0.f;
#pragma unroll 8
            for (int h = 0; h < H; ++h) acc = fmaf(x[h], W_r[h * H + j], acc);
            g_h_rel[rr * H + j] = acc;
            float p = acc * avec[2 * H + j];
#pragma unroll
            for (int off = 16; off; off >>= 1) p += __shfl_xor_sync(0xffffffffu, p, off);
            if ((tid & 31) == 0) D[tid >> 5] = p;
        }
        __syncthreads();
        if ((tid & 127) == 0 && rr < nrel) {
            int b = (tid >> 7) * 4;
            g_s_rel[rr] = D[b] + D[b + 1] + D[b + 2] + D[b + 3];
        }
    }

    // ---- stage B once (uint4 copy of pre-converted arrays) ----
    {
        const uint4* bh = (const uint4*)(const void*)g_BW_hi;
        const uint4* bl = (const uint4*)(const void*)g_BW_lo;
        uint4* dh = (uint4*)(sm + SM_BHI);
        uint4* dl = (uint4*)(sm + SM_BLO);
        for (int i = tid; i < (H * K_PAD * 2) / 16; i += 256) { dh[i] = bh[i]; dl[i] = bl[i]; }
    }

    const float4* X4 = (const float4*)Xin;
    uint32_t a_loff = (uint32_t)(((lrow + (quad & 1) * 8) * K_PAD + (quad >> 1) * 8) * 2);
    uint32_t b_loff = (uint32_t)(((lrow + (quad >> 1) * 8) * K_PAD + (quad & 1) * 8) * 2);

    float4 pre[8];
    {
        int t0 = blockIdx.x, row0 = t0 * TILE_M;
#pragma unroll
        for (int it = 0; it < 8; ++it) {
            int idx = it * 256 + tid;
            int r = idx >> 5, s = idx & 31;
            int row = row0 + r;
            pre[it] = make_float4(0.f, 0.f, 0.f, 0.f);
            if (t0 < ntiles && row < n) pre[it] = X4[(size_t)row * 32 + s];
        }
    }

    for (int t = blockIdx.x; t < ntiles; t += GRID_GEMM) {
        int row0 = t * TILE_M;
        __syncthreads();

#pragma unroll
        for (int it = 0; it < 8; ++it) {
            int idx = it * 256 + tid;
            int r = idx >> 5, s = idx & 31;
            float4 v = pre[it];
            __nv_bfloat16 h0 = __float2bfloat16_rn(v.x);
            __nv_bfloat16 h1 = __float2bfloat16_rn(v.y);
            __nv_bfloat16 h2 = __float2bfloat16_rn(v.z);
            __nv_bfloat16 h3 = __float2bfloat16_rn(v.w);
            __nv_bfloat162 ph0 = __halves2bfloat162(h0, h1);
            __nv_bfloat162 ph1 = __halves2bfloat162(h2, h3);
            uint2 uh; uh.x = *(uint32_t*)&ph0; uh.y = *(uint32_t*)&ph1;
            *(uint2*)(Ahi + r * K_PAD + 4 * s) = uh;
            __nv_bfloat162 pl0 = __halves2bfloat162(
                __float2bfloat16_rn(v.x - __bfloat162float(h0)),
                __float2bfloat16_rn(v.y - __bfloat162float(h1)));
            __nv_bfloat162 pl1 = __halves2bfloat162(
                __float2bfloat16_rn(v.z - __bfloat162float(h2)),
                __float2bfloat16_rn(v.w - __bfloat162float(h3)));
            uint2 ul; ul.x = *(uint32_t*)&pl0; ul.y = *(uint32_t*)&pl1;
            *(uint2*)(Alo + r * K_PAD + 4 * s) = ul;
        }
        __syncthreads();

        {
            int tn = t + GRID_GEMM, nrow0 = tn * TILE_M;
#pragma unroll
            for (int it = 0; it < 8; ++it) {
                int idx = it * 256 + tid;
                int r = idx >> 5, s = idx & 31;
                int row = nrow0 + r;
                pre[it] = make_float4(0.f, 0.f, 0.f, 0.f);
                if (tn < ntiles && row < n) pre[it] = X4[(size_t)row * 32 + s];
            }
        }

        float acc[2][4][4];
#pragma unroll
        for (int i = 0; i < 2; i++)
#pragma unroll
            for (int j = 0; j < 4; j++)
#pragma unroll
                for (int q = 0; q < 4; q++) acc[i][j][q] = 0.f;

#pragma unroll
        for (int pass = 0; pass < 3; pass++) {
            uint32_t abase = sb + ((pass == 2) ? SM_ALO : SM_A);
            uint32_t bbase = sb + ((pass == 1) ? SM_BLO : SM_BHI);
            uint32_t arow = abase + (uint32_t)(wm * 32) * (K_PAD * 2) + a_loff;
            uint32_t brow = bbase + (uint32_t)(wn * 32) * (K_PAD * 2) + b_loff;
#pragma unroll
            for (int ks = 0; ks < 8; ks++) {
                uint32_t k0 = ks * 32;
                uint32_t af[2][4], bf[2][4];
#pragma unroll
                for (int mt = 0; mt < 2; mt++)
                    LDMX4(af[mt][0], af[mt][1], af[mt][2], af[mt][3],
                          arow + (uint32_t)(mt * 16) * (K_PAD * 2) + k0);
#pragma unroll
                for (int nt = 0; nt < 2; nt++)
                    LDMX4(bf[nt][0], bf[nt][1], bf[nt][2], bf[nt][3],
                          brow + (uint32_t)(nt * 16) * (K_PAD * 2) + k0);
#pragma unroll
                for (int mt = 0; mt < 2; mt++)
#pragma unroll
                    for (int q = 0; q < 4; q++)
                        mma16816(acc[mt][q], af[mt][0], af[mt][1], af[mt][2], af[mt][3],
                                 bf[q >> 1][(q & 1) * 2], bf[q >> 1][(q & 1) * 2 + 1]);
            }
        }
        __syncthreads();

#pragma unroll
        for (int mt = 0; mt < 2; mt++) {
            int row = wm * 32 + mt * 16 + (l >> 2);
#pragma unroll
            for (int q = 0; q < 4; q++) {
                int col = wn * 32 + q * 8 + 2 * (l & 3);
                *(float2*)(D + row * D_PAD + col) = make_float2(acc[mt][q][0], acc[mt][q][1]);
                *(float2*)(D + (row + 8) * D_PAD + col) = make_float2(acc[mt][q][2], acc[mt][q][3]);
            }
        }
        __syncthreads();

#pragma unroll
        for (int it = 0; it < 8; ++it) {
            int idx = it * 256 + tid;
            int r = idx >> 5, s = idx & 31;
            int row = row0 + r;
            if (row < n) {
                float4 v = *(float4*)(D + r * D_PAD + 4 * s);
                *(float4*)(g_h_node + (size_t)row * H + 4 * s) = v;
            }
        }
        if (tid < 128) {
            int r = tid & 63;
            int row = row0 + r;
            if (row < n) {
                const float* av = (tid < 64) ? a1s : a2s;
                float p = 0.f;
                const float* dr = D + r * D_PAD;
#pragma unroll 8
                for (int c = 0; c < H; c++) p = fmaf(dr[c], av[c], p);
                if (tid < 64) g_s_src[row] = p; else g_s_dst[row] = p;
            }
        }
    }
}

// ====== kgather: score -> top10 -> softmax -> gather -> bf16 hi/lo out ====
#define G_WARPS 8
__global__ void __launch_bounds__(256) kgather(const int* __restrict__ src,
                                               const int* __restrict__ rid, int n) {
    __shared__ float ats[G_WARPS][16];
    __shared__ int   sks[G_WARPS][16];
    __shared__ int   rks[G_WARPS][16];
    int tid = threadIdx.x;
    int w = tid >> 5, l = tid & 31;
    int node = blockIdx.x * G_WARPS + w;
    if (node >= n) return;

    float sdst = g_s_dst[node];
    int s = src[node * DEG + l];
    int r = rid[node * DEG + l];
    float v = (g_s_src[s] + sdst) + g_s_rel[r];
    float sc = (v >= 0.f) ? v : 0.2f * v;

    int rank = 0;
#pragma unroll
    for (int j = 0; j < DEG; j++) {
        float vj = __shfl_sync(0xffffffffu, sc, j);
        rank += (vj > sc) || (vj == sc && j < l);
    }
    bool sel = (rank < TOPK);

    float m = sel ? sc : __int_as_float(0xff800000);
#pragma unroll
    for (int off = 16; off; off >>= 1) m = fmaxf(m, __shfl_xor_sync(0xffffffffu, m, off));
    float e = sel ? expf(sc - m) : 0.f;
    float z = e;
#pragma unroll
    for (int off = 16; off; off >>= 1) z += __shfl_xor_sync(0xffffffffu, z, off);
    float attn = e / z;

    if (sel) { ats[w][rank] = attn; sks[w][rank] = s; rks[w][rank] = r; }
    __syncwarp();

    float4 acc = make_float4(0.f, 0.f, 0.f, 0.f);
#pragma unroll
    for (int k = 0; k < TOPK; k++) {
        int sk = sks[w][k], rk = rks[w][k];
        float ak = ats[w][k];
        float4 hn = __ldcg((const float4*)(g_h_node + (size_t)sk * H + 4 * l));
        float4 hr = *(const float4*)(g_h_rel + rk * H + 4 * l);
        acc.x = fmaf(ak, hn.x + hr.x, acc.x);
        acc.y = fmaf(ak, hn.y + hr.y, acc.y);
        acc.z = fmaf(ak, hn.z + hr.z, acc.z);
        acc.w = fmaf(ak, hn.w + hr.w, acc.w);
    }

    // split to bf16 hi/lo here (bit-identical to splitting in kgemm1)
    __nv_bfloat16 h0 = __float2bfloat16_rn(acc.x);
    __nv_bfloat16 h1 = __float2bfloat16_rn(acc.y);
    __nv_bfloat16 h2 = __float2bfloat16_rn(acc.z);
    __nv_bfloat16 h3 = __float2bfloat16_rn(acc.w);
    __nv_bfloat162 ph0 = __halves2bfloat162(h0, h1);
    __nv_bfloat162 ph1 = __halves2bfloat162(h2, h3);
    uint2 uh; uh.x = *(uint32_t*)&ph0; uh.y = *(uint32_t*)&ph1;
    *(uint2*)(g_nA_hi + (size_t)node * H + 4 * l) = uh;
    __nv_bfloat162 pl0 = __halves2bfloat162(
        __float2bfloat16_rn(acc.x - __bfloat162float(h0)),
        __float2bfloat16_rn(acc.y - __bfloat162float(h1)));
    __nv_bfloat162 pl1 = __halves2bfloat162(
        __float2bfloat16_rn(acc.z - __bfloat162float(h2)),
        __float2bfloat16_rn(acc.w - __bfloat162float(h3)));
    uint2 ul; ul.x = *(uint32_t*)&pl0; ul.y = *(uint32_t*)&pl1;
    *(uint2*)(g_nA_lo + (size_t)node * H + 4 * l) = ul;
}

// ====== kgemm1: out = tanh(neigh @ neigh_w) ===============================
// A pre-split by kgather; staged via cp.async overlapped with the epilogue;
// epilogue goes straight from MMA accumulators to gmem (no D staging).
__device__ __forceinline__ void kg1_prefetch(uint32_t sbA, uint32_t sbAlo,
                                             int tile, int tid) {
    const char* nh = (const char*)(g_nA_hi + (size_t)tile * TILE_M * H);
    const char* nl = (const char*)(g_nA_lo + (size_t)tile * TILE_M * H);
#pragma unroll
    for (int it = 0; it < 4; ++it) {
        int idx = it * 256 + tid;        // 1024 uint4 per buffer
        int r = idx >> 4, s = idx & 15;
        uint32_t doff = (uint32_t)(r * (K_PAD * 2) + 16 * s);
        CPASYNC16(sbA + doff,   nh + idx * 16);
        CPASYNC16(sbAlo + doff, nl + idx * 16);
    }
    CPASYNC_COMMIT();
}

__global__ void __launch_bounds__(256, 2) kgemm1(float* __restrict__ out,
                                                 int n, int ntiles) {
    extern __shared__ char sm[];
    uint32_t sb = smem_u32(sm);
    int tid = threadIdx.x;
    int w = tid >> 5, l = tid & 31;
    int wm = w >> 2, wn = w & 3;
    int quad = l >> 3, lrow = l & 7;

    // ---- stage B once (uint4 copy of pre-converted arrays) ----
    {
        const uint4* bh = (const uint4*)(const void*)g_BN_hi;
        const uint4* bl = (const uint4*)(const void*)g_BN_lo;
        uint4* dh = (uint4*)(sm + SM_BHI);
        uint4* dl = (uint4*)(sm + SM_BLO);
        for (int i = tid; i < (H * K_PAD * 2) / 16; i += 256) { dh[i] = bh[i]; dl[i] = bl[i]; }
    }

    uint32_t a_loff = (uint32_t)(((lrow + (quad & 1) * 8) * K_PAD + (quad >> 1) * 8) * 2);
    uint32_t b_loff = (uint32_t)(((lrow + (quad >> 1) * 8) * K_PAD + (quad & 1) * 8) * 2);

    // prefetch first tile
    if (blockIdx.x < ntiles) kg1_prefetch(sb + SM_A, sb + SM_ALO, blockIdx.x, tid);

    for (int t = blockIdx.x; t < ntiles; t += GRID_GEMM) {
        int row0 = t * TILE_M;
        CPASYNC_WAIT0();
        __syncthreads();                 // A tile + B ready; prev epilogue done

        float acc[2][4][4];
#pragma unroll
        for (int i = 0; i < 2; i++)
#pragma unroll
            for (int j = 0; j < 4; j++)
#pragma unroll
                for (int q = 0; q < 4; q++) acc[i][j][q] = 0.f;

#pragma unroll
        for (int pass = 0; pass < 3; pass++) {
            uint32_t abase = sb + ((pass == 2) ? SM_ALO : SM_A);
            uint32_t bbase = sb + ((pass == 1) ? SM_BLO : SM_BHI);
            uint32_t arow = abase + (uint32_t)(wm * 32) * (K_PAD * 2) + a_loff;
            uint32_t brow = bbase + (uint32_t)(wn * 32) * (K_PAD * 2) + b_loff;
#pragma unroll
            for (int ks = 0; ks < 8; ks++) {
                uint32_t k0 = ks * 32;
                uint32_t af[2][4], bf[2][4];
#pragma unroll
                for (int mt = 0; mt < 2; mt++)
                    LDMX4(af[mt][0], af[mt][1], af[mt][2], af[mt][3],
                          arow + (uint32_t)(mt * 16) * (K_PAD * 2) + k0);
#pragma unroll
                for (int nt = 0; nt < 2; nt++)
                    LDMX4(bf[nt][0], bf[nt][1], bf[nt][2], bf[nt][3],
                          brow + (uint32_t)(nt * 16) * (K_PAD * 2) + k0);
#pragma unroll
                for (int mt = 0; mt < 2; mt++)
#pragma unroll
                    for (int q = 0; q < 4; q++)
                        mma16816(acc[mt][q], af[mt][0], af[mt][1], af[mt][2], af[mt][3],
                                 bf[q >> 1][(q & 1) * 2], bf[q >> 1][(q & 1) * 2 + 1]);
            }
        }
        __syncthreads();                 // all ldmatrix reads done; A free

        // ---- prefetch next tile's A (overlaps with epilogue below) ----
        {
            int tn = t + GRID_GEMM;
            if (tn < ntiles) kg1_prefetch(sb + SM_A, sb + SM_ALO, tn, tid);
        }

        // ---- epilogue: tanh straight from accumulators ----
#pragma unroll
        for (int mt = 0; mt < 2; mt++) {
            int row = row0 + wm * 32 + mt * 16 + (l >> 2);
#pragma unroll
            for (int q = 0; q < 4; q++) {
                int col = wn * 32 + q * 8 + 2 * (l & 3);
                if (row < n)
                    *(float2*)(out + (size_t)row * H + col) =
                        make_float2(tanhf(acc[mt][q][0]), tanhf(acc[mt][q][1]));
                if (row + 8 < n)
                    *(float2*)(out + (size_t)(row + 8) * H + col) =
                        make_float2(tanhf(acc[mt][q][2]), tanhf(acc[mt][q][3]));
            }
        }
    }
}

// ============================== launch =====================================
extern "C" void kernel_launch(void* const* d_in, const int* in_sizes, int n_in,
                              void* d_out, int out_size) {
    const float* ent = (const float*)d_in[0];
    const float* rel = (const float*)d_in[1];
    const float* W   = (const float*)d_in[2];
    const float* W_r = (const float*)d_in[3];
    const float* a   = (const float*)d_in[4];
    const float* nw  = (const float*)d_in[5];
    const int*   src = (const int*)d_in[6];
    const int*   rid = (const int*)d_in[7];
    float* out = (float*)d_out;

    int n    = in_sizes[0] / H;   // 150000
    int nrel = in_sizes[1] / H;   // 500
    int ntiles = (n + TILE_M - 1) / TILE_M;

    cudaFuncSetAttribute(kgemm0, cudaFuncAttributeMaxDynamicSharedMemorySize, SM_TOTAL);
    cudaFuncSetAttribute(kgemm1, cudaFuncAttributeMaxDynamicSharedMemorySize, SM_TOTAL);

    kprepB<<<(H * H + 255) / 256, 256>>>(W, nw);
    kgemm0<<<GRID_GEMM, 256, SM_TOTAL>>>(ent, a, rel, W_r, n, ntiles, nrel);
    kgather<<<(n + G_WARPS - 1) / G_WARPS, 256>>>(src, rid, n);
    kgemm1<<<GRID_GEMM, 256, SM_TOTAL>>>(out, n, ntiles);
}